// round 16
// baseline (speedup 1.0000x reference)
#include <cuda_runtime.h>

#define N_NODES 50000
#define N_EDGES 800000
#define NODE_DIM 64
#define HIDDEN 128
#define OUT_DIM 256
#define N_LAYERS 3
#define SCAN_BLOCKS ((N_NODES + 255) / 256)   // 196
#define RED_BLOCKS 512

typedef unsigned long long u64;

// Scratch (static device globals; no runtime allocation)
__device__ float d_hbuf0[(size_t)N_NODES * HIDDEN];
__device__ float d_hbuf1[(size_t)N_NODES * HIDDEN];
__device__ float d_deg[N_NODES];      // 1/deg (0 for isolated nodes)
__device__ float d_gsum[HIDDEN];      // reset by scan3 each call
__device__ int   d_cnt[N_NODES];      // histogram; reset by scan3 each call
__device__ int   d_row[N_NODES + 1];  // CSR row offsets
__device__ int   d_cur[N_NODES];      // fill cursors
__device__ int   d_colA[N_EDGES];     // CSR column (src node per edge slot)
__device__ int   d_bsum[SCAN_BLOCKS];

// ---- packed f32x2 helpers (Blackwell dual-FMA) -----------------------------
__device__ __forceinline__ u64 pack2(float lo, float hi) {
    u64 r;
    asm("mov.b64 %0, {%1, %2};" : "=l"(r)
        : "r"(__float_as_uint(lo)), "r"(__float_as_uint(hi)));
    return r;
}
__device__ __forceinline__ void unpack2(u64 v, float& lo, float& hi) {
    unsigned int a, b;
    asm("mov.b64 {%0, %1}, %2;" : "=r"(a), "=r"(b) : "l"(v));
    lo = __uint_as_float(a);
    hi = __uint_as_float(b);
}
__device__ __forceinline__ void fma2(u64& acc, u64 a, u64 b) {
    asm("fma.rn.f32x2 %0, %1, %2, %0;" : "+l"(acc) : "l"(a), "l"(b));
}

// ---------------------------------------------------------------------------
__global__ void hist_kernel(const int* __restrict__ dst) {
    int e = blockIdx.x * blockDim.x + threadIdx.x;
    if (e < N_EDGES) atomicAdd(&d_cnt[dst[e]], 1);
}

__global__ void scan1_kernel() {
    __shared__ int sd[256];
    int t = threadIdx.x;
    int i = blockIdx.x * 256 + t;
    int v = (i < N_NODES) ? d_cnt[i] : 0;
    sd[t] = v;
    __syncthreads();
#pragma unroll
    for (int off = 1; off < 256; off <<= 1) {
        int a = (t >= off) ? sd[t - off] : 0;
        __syncthreads();
        sd[t] += a;
        __syncthreads();
    }
    if (i < N_NODES) d_row[i] = sd[t] - v;   // exclusive
    if (t == 255) d_bsum[blockIdx.x] = sd[t];
}

__global__ void scan2_kernel() {
    __shared__ int sd[256];
    int t = threadIdx.x;
    int v = (t < SCAN_BLOCKS) ? d_bsum[t] : 0;
    sd[t] = v;
    __syncthreads();
#pragma unroll
    for (int off = 1; off < 256; off <<= 1) {
        int a = (t >= off) ? sd[t - off] : 0;
        __syncthreads();
        sd[t] += a;
        __syncthreads();
    }
    if (t < SCAN_BLOCKS) d_bsum[t] = sd[t] - v;  // exclusive
}

// scan3 also self-resets d_cnt and d_gsum (replaces init_kernel).
__global__ void scan3_kernel() {
    int i = blockIdx.x * blockDim.x + threadIdx.x;
    if (i < N_NODES) {
        int r = d_row[i] + d_bsum[blockIdx.x];
        d_row[i] = r;
        d_cur[i] = r;
        int c = d_cnt[i];
        d_deg[i] = (c > 0) ? (1.0f / (float)c) : 0.0f;
        d_cnt[i] = 0;                  // self-reset for next replay
    }
    if (i == 0) d_row[N_NODES] = N_EDGES;
    if (i < HIDDEN) d_gsum[i] = 0.0f;  // reset before reduce accumulates
}

__global__ void fill_kernel(const int* __restrict__ src, const int* __restrict__ dst) {
    int e = blockIdx.x * blockDim.x + threadIdx.x;
    if (e < N_EDGES) {
        int d = dst[e];
        int pos = atomicAdd(&d_cur[d], 1);
        d_colA[pos] = src[e];
    }
}

// ---------------------------------------------------------------------------
// h0 = x @ Wp + bp   (x: [N,64], Wp: [64,128]) -> d_hbuf0
// 128 threads, 32 nodes; thread (nt,ct) owns 8 nodes x 4 cols.
__global__ void __launch_bounds__(128) proj_kernel(const float* __restrict__ x,
                            const float* __restrict__ Wp,
                            const float* __restrict__ bp) {
    __shared__ float xs[32][NODE_DIM];
    int t = threadIdx.x;
    int node0 = blockIdx.x * 32;

    for (int i = t; i < 32 * (NODE_DIM / 4); i += 128) {
        int r = i >> 4;
        int c4 = i & 15;
        int node = node0 + r;
        float4 v = make_float4(0.f, 0.f, 0.f, 0.f);
        if (node < N_NODES)
            v = ((const float4*)(x + (size_t)node * NODE_DIM))[c4];
        *(float4*)&xs[r][c4 * 4] = v;
    }
    __syncthreads();

    int ct = t & 31;
    int nt = t >> 5;
    int colb = ct * 4;

    u64 acc2[8][2];
#pragma unroll
    for (int i = 0; i < 8; i++) { acc2[i][0] = 0ull; acc2[i][1] = 0ull; }

    const float4* W4 = (const float4*)Wp;
#pragma unroll 4
    for (int k = 0; k < NODE_DIM; k++) {
        float4 w = W4[k * 32 + ct];
        u64 wp0 = pack2(w.x, w.y);
        u64 wp1 = pack2(w.z, w.w);
#pragma unroll
        for (int i = 0; i < 8; i++) {
            float m = xs[nt * 8 + i][k];
            u64 mp = pack2(m, m);
            fma2(acc2[i][0], mp, wp0);
            fma2(acc2[i][1], mp, wp1);
        }
    }

    float4 bv = ((const float4*)bp)[ct];
#pragma unroll
    for (int i = 0; i < 8; i++) {
        int node = node0 + nt * 8 + i;
        if (node < N_NODES) {
            float4 r;
            unpack2(acc2[i][0], r.x, r.y);
            unpack2(acc2[i][1], r.z, r.w);
            r.x += bv.x; r.y += bv.y; r.z += bv.z; r.w += bv.w;
            *(float4*)(d_hbuf0 + (size_t)node * HIDDEN + colb) = r;
        }
    }
}

// ---------------------------------------------------------------------------
// Fused GNN layer: hout = relu(hin + (gather_mean(hin) @ Wg) + bg)
// R15-champion: two-node interleaved gather (8 LDG.128 in flight) + warp-local
// barrier (GEMM reads only own-warp ms rows) + packed-fma2 GEMM.
__global__ void __launch_bounds__(128) layer_kernel(const float* __restrict__ hin,
                             float* __restrict__ hout,
                             const float* __restrict__ Wg,
                             const float* __restrict__ bg) {
    __shared__ float ms[32][HIDDEN];
    int t = threadIdx.x;
    int node0 = blockIdx.x * 32;
    int lane = t & 31;
    int w = t >> 5;   // warp 0..3

#pragma unroll 1
    for (int ii = 0; ii < 8; ii += 2) {
        int nlA = w * 8 + ii;
        int nlB = nlA + 1;
        int nA = node0 + nlA;
        int nB = node0 + nlB;

        float4 aA0 = make_float4(0.f, 0.f, 0.f, 0.f), aA1 = aA0;
        float4 aB0 = aA0, aB1 = aA0;

        int jA = 0, eA = 0, jB = 0, eB = 0;
        float invA = 0.0f, invB = 0.0f;
        if (nA < N_NODES) { jA = d_row[nA]; eA = d_row[nA + 1]; invA = d_deg[nA]; }
        if (nB < N_NODES) { jB = d_row[nB]; eB = d_row[nB + 1]; invB = d_deg[nB]; }

        // Joint loop: 4 edges from A + 4 edges from B per iteration.
#pragma unroll 1
        while (jA + 4 <= eA && jB + 4 <= eB) {
            int sA0 = d_colA[jA],     sA1 = d_colA[jA + 1];
            int sA2 = d_colA[jA + 2], sA3 = d_colA[jA + 3];
            int sB0 = d_colA[jB],     sB1 = d_colA[jB + 1];
            int sB2 = d_colA[jB + 2], sB3 = d_colA[jB + 3];
            float4 vA0 = ((const float4*)(hin + (size_t)sA0 * HIDDEN))[lane];
            float4 vA1 = ((const float4*)(hin + (size_t)sA1 * HIDDEN))[lane];
            float4 vA2 = ((const float4*)(hin + (size_t)sA2 * HIDDEN))[lane];
            float4 vA3 = ((const float4*)(hin + (size_t)sA3 * HIDDEN))[lane];
            float4 vB0 = ((const float4*)(hin + (size_t)sB0 * HIDDEN))[lane];
            float4 vB1 = ((const float4*)(hin + (size_t)sB1 * HIDDEN))[lane];
            float4 vB2 = ((const float4*)(hin + (size_t)sB2 * HIDDEN))[lane];
            float4 vB3 = ((const float4*)(hin + (size_t)sB3 * HIDDEN))[lane];
            aA0.x += vA0.x; aA0.y += vA0.y; aA0.z += vA0.z; aA0.w += vA0.w;
            aA1.x += vA1.x; aA1.y += vA1.y; aA1.z += vA1.z; aA1.w += vA1.w;
            aA0.x += vA2.x; aA0.y += vA2.y; aA0.z += vA2.z; aA0.w += vA2.w;
            aA1.x += vA3.x; aA1.y += vA3.y; aA1.z += vA3.z; aA1.w += vA3.w;
            aB0.x += vB0.x; aB0.y += vB0.y; aB0.z += vB0.z; aB0.w += vB0.w;
            aB1.x += vB1.x; aB1.y += vB1.y; aB1.z += vB1.z; aB1.w += vB1.w;
            aB0.x += vB2.x; aB0.y += vB2.y; aB0.z += vB2.z; aB0.w += vB2.w;
            aB1.x += vB3.x; aB1.y += vB3.y; aB1.z += vB3.z; aB1.w += vB3.w;
            jA += 4; jB += 4;
        }
        // Drain A (unroll-4 then singles)
#pragma unroll 1
        while (jA + 4 <= eA) {
            int s0 = d_colA[jA],     s1 = d_colA[jA + 1];
            int s2 = d_colA[jA + 2], s3 = d_colA[jA + 3];
            float4 v0 = ((const float4*)(hin + (size_t)s0 * HIDDEN))[lane];
            float4 v1 = ((const float4*)(hin + (size_t)s1 * HIDDEN))[lane];
            float4 v2 = ((const float4*)(hin + (size_t)s2 * HIDDEN))[lane];
            float4 v3 = ((const float4*)(hin + (size_t)s3 * HIDDEN))[lane];
            aA0.x += v0.x; aA0.y += v0.y; aA0.z += v0.z; aA0.w += v0.w;
            aA1.x += v1.x; aA1.y += v1.y; aA1.z += v1.z; aA1.w += v1.w;
            aA0.x += v2.x; aA0.y += v2.y; aA0.z += v2.z; aA0.w += v2.w;
            aA1.x += v3.x; aA1.y += v3.y; aA1.z += v3.z; aA1.w += v3.w;
            jA += 4;
        }
#pragma unroll 1
        while (jA < eA) {
            int s = d_colA[jA++];
            float4 v = ((const float4*)(hin + (size_t)s * HIDDEN))[lane];
            aA0.x += v.x; aA0.y += v.y; aA0.z += v.z; aA0.w += v.w;
        }
        // Drain B
#pragma unroll 1
        while (jB + 4 <= eB) {
            int s0 = d_colA[jB],     s1 = d_colA[jB + 1];
            int s2 = d_colA[jB + 2], s3 = d_colA[jB + 3];
            float4 v0 = ((const float4*)(hin + (size_t)s0 * HIDDEN))[lane];
            float4 v1 = ((const float4*)(hin + (size_t)s1 * HIDDEN))[lane];
            float4 v2 = ((const float4*)(hin + (size_t)s2 * HIDDEN))[lane];
            float4 v3 = ((const float4*)(hin + (size_t)s3 * HIDDEN))[lane];
            aB0.x += v0.x; aB0.y += v0.y; aB0.z += v0.z; aB0.w += v0.w;
            aB1.x += v1.x; aB1.y += v1.y; aB1.z += v1.z; aB1.w += v1.w;
            aB0.x += v2.x; aB0.y += v2.y; aB0.z += v2.z; aB0.w += v2.w;
            aB1.x += v3.x; aB1.y += v3.y; aB1.z += v3.z; aB1.w += v3.w;
            jB += 4;
        }
#pragma unroll 1
        while (jB < eB) {
            int s = d_colA[jB++];
            float4 v = ((const float4*)(hin + (size_t)s * HIDDEN))[lane];
            aB0.x += v.x; aB0.y += v.y; aB0.z += v.z; aB0.w += v.w;
        }

        float4 rA, rB;
        rA.x = (aA0.x + aA1.x) * invA; rA.y = (aA0.y + aA1.y) * invA;
        rA.z = (aA0.z + aA1.z) * invA; rA.w = (aA0.w + aA1.w) * invA;
        rB.x = (aB0.x + aB1.x) * invB; rB.y = (aB0.y + aB1.y) * invB;
        rB.z = (aB0.z + aB1.z) * invB; rB.w = (aB0.w + aB1.w) * invB;
        *(float4*)&ms[nlA][lane * 4] = rA;
        *(float4*)&ms[nlB][lane * 4] = rB;
    }
    __syncwarp();   // warp-local: GEMM below reads only this warp's ms rows

    // Phase 2: (ms @ Wg) — thread (nt=w, ct=lane) owns 8 nodes x 4 cols
    int ct = lane;
    int nt = w;
    int colb = ct * 4;

    u64 acc2[8][2];
#pragma unroll
    for (int i = 0; i < 8; i++) { acc2[i][0] = 0ull; acc2[i][1] = 0ull; }

    const float4* W4 = (const float4*)Wg;
#pragma unroll 4
    for (int k = 0; k < HIDDEN; k++) {
        float4 wv = W4[k * 32 + ct];
        u64 wp0 = pack2(wv.x, wv.y);
        u64 wp1 = pack2(wv.z, wv.w);
#pragma unroll
        for (int i = 0; i < 8; i++) {
            float m = ms[nt * 8 + i][k];
            u64 mp = pack2(m, m);
            fma2(acc2[i][0], mp, wp0);
            fma2(acc2[i][1], mp, wp1);
        }
    }

    float4 bv = ((const float4*)bg)[ct];
#pragma unroll
    for (int i = 0; i < 8; i++) {
        int node = node0 + nt * 8 + i;
        if (node < N_NODES) {
            float4 hv = *(const float4*)(hin + (size_t)node * HIDDEN + colb);
            float lo, hi;
            float4 r;
            unpack2(acc2[i][0], lo, hi);
            r.x = fmaxf(hv.x + lo + bv.x, 0.0f);
            r.y = fmaxf(hv.y + hi + bv.y, 0.0f);
            unpack2(acc2[i][1], lo, hi);
            r.z = fmaxf(hv.z + lo + bv.z, 0.0f);
            r.w = fmaxf(hv.w + hi + bv.w, 0.0f);
            *(float4*)(hout + (size_t)node * HIDDEN + colb) = r;
        }
    }
}

// ---------------------------------------------------------------------------
// Column sums of h into d_gsum. Warp w of block b reads row b*8+w as 32
// coalesced float4 (512B per warp-instruction); grid-stride over nodes.
__global__ void __launch_bounds__(256) reduce_kernel(const float* __restrict__ h) {
    int t = threadIdx.x;
    int lane = t & 31;      // float4 column group 0..31
    int w = t >> 5;         // warp 0..7 -> row within iteration
    float4 acc = make_float4(0.f, 0.f, 0.f, 0.f);
#pragma unroll 1
    for (int node = blockIdx.x * 8 + w; node < N_NODES; node += RED_BLOCKS * 8) {
        float4 v = ((const float4*)(h + (size_t)node * HIDDEN))[lane];
        acc.x += v.x; acc.y += v.y; acc.z += v.z; acc.w += v.w;
    }
    atomicAdd(&d_gsum[lane * 4 + 0], acc.x);
    atomicAdd(&d_gsum[lane * 4 + 1], acc.y);
    atomicAdd(&d_gsum[lane * 4 + 2], acc.z);
    atomicAdd(&d_gsum[lane * 4 + 3], acc.w);
}

__global__ void mlp_kernel(const float* __restrict__ W1,
                           const float* __restrict__ b1,
                           const float* __restrict__ W2,
                           const float* __restrict__ b2,
                           float* __restrict__ out) {
    __shared__ float gs[HIDDEN];
    __shared__ float ts[HIDDEN];
    int t = threadIdx.x;  // 256
    if (t < HIDDEN) gs[t] = d_gsum[t] * (1.0f / (float)N_NODES);
    __syncthreads();
    if (t < HIDDEN) {
        float a = b1[t];
#pragma unroll 8
        for (int k = 0; k < HIDDEN; k++) a += gs[k] * W1[k * HIDDEN + t];
        ts[t] = fmaxf(a, 0.0f);
    }
    __syncthreads();
    {
        float a = b2[t];
#pragma unroll 8
        for (int k = 0; k < HIDDEN; k++) a += ts[k] * W2[k * OUT_DIM + t];
        out[t] = a;
    }
}

// ---------------------------------------------------------------------------
extern "C" void kernel_launch(void* const* d_in, const int* in_sizes, int n_in,
                              void* d_out, int out_size) {
    const float* x   = (const float*)d_in[0];
    const int*   src = (const int*)d_in[1];
    const int*   dst = (const int*)d_in[2];
    const float* Wp  = (const float*)d_in[3];
    const float* bp  = (const float*)d_in[4];
    const float* Wg  = (const float*)d_in[5];
    const float* bg  = (const float*)d_in[6];
    const float* W1  = (const float*)d_in[7];
    const float* b1  = (const float*)d_in[8];
    const float* W2  = (const float*)d_in[9];
    const float* b2  = (const float*)d_in[10];
    float* out = (float*)d_out;

    float *h0, *h1;
    cudaGetSymbolAddress((void**)&h0, d_hbuf0);
    cudaGetSymbolAddress((void**)&h1, d_hbuf1);

    // CSR build (init folded into scan3)
    hist_kernel<<<(N_EDGES + 255) / 256, 256>>>(dst);
    scan1_kernel<<<SCAN_BLOCKS, 256>>>();
    scan2_kernel<<<1, 256>>>();
    scan3_kernel<<<SCAN_BLOCKS, 256>>>();
    fill_kernel<<<(N_EDGES + 255) / 256, 256>>>(src, dst);

    // node projection
    proj_kernel<<<(N_NODES + 31) / 32, 128>>>(x, Wp, bp);

    // GNN layers with ping-pong buffers
    const int nblocks = (N_NODES + 31) / 32;
    float* bufs[2] = {h0, h1};
    for (int l = 0; l < N_LAYERS; l++) {
        float* hin  = bufs[l & 1];
        float* hout = bufs[(l + 1) & 1];
        layer_kernel<<<nblocks, 128>>>(hin, hout,
                                       Wg + (size_t)l * HIDDEN * HIDDEN,
                                       bg + (size_t)l * HIDDEN);
    }

    // mean over nodes + MLP head
    reduce_kernel<<<RED_BLOCKS, 256>>>(bufs[N_LAYERS & 1]);
    mlp_kernel<<<1, 256>>>(W1, b1, W2, b2, out);
}

// round 17
// speedup vs baseline: 1.2036x; 1.2036x over previous
#include <cuda_runtime.h>

#define N_NODES 50000
#define N_EDGES 800000
#define NODE_DIM 64
#define HIDDEN 128
#define OUT_DIM 256
#define N_LAYERS 3
#define SCAN_BLOCKS ((N_NODES + 255) / 256)   // 196

typedef unsigned long long u64;

// Scratch (static device globals; no runtime allocation)
__device__ float d_hbuf0[(size_t)N_NODES * HIDDEN];
__device__ float d_hbuf1[(size_t)N_NODES * HIDDEN];
__device__ float d_deg[N_NODES];      // 1/deg (0 for isolated nodes)
__device__ float d_gsum[HIDDEN];      // reset by scan3 each call
__device__ int   d_cnt[N_NODES];      // histogram; reset by scan3 each call
__device__ int   d_row[N_NODES + 1];  // CSR row offsets
__device__ int   d_cur[N_NODES];      // fill cursors
__device__ int   d_colA[N_EDGES];     // CSR column (src node per edge slot)
__device__ int   d_bsum[SCAN_BLOCKS];

// ---- packed f32x2 helpers (Blackwell dual-FMA) -----------------------------
__device__ __forceinline__ u64 pack2(float lo, float hi) {
    u64 r;
    asm("mov.b64 %0, {%1, %2};" : "=l"(r)
        : "r"(__float_as_uint(lo)), "r"(__float_as_uint(hi)));
    return r;
}
__device__ __forceinline__ void unpack2(u64 v, float& lo, float& hi) {
    unsigned int a, b;
    asm("mov.b64 {%0, %1}, %2;" : "=r"(a), "=r"(b) : "l"(v));
    lo = __uint_as_float(a);
    hi = __uint_as_float(b);
}
__device__ __forceinline__ void fma2(u64& acc, u64 a, u64 b) {
    asm("fma.rn.f32x2 %0, %1, %2, %0;" : "+l"(acc) : "l"(a), "l"(b));
}

// ---------------------------------------------------------------------------
__global__ void hist_kernel(const int* __restrict__ dst) {
    int e = blockIdx.x * blockDim.x + threadIdx.x;
    if (e < N_EDGES) atomicAdd(&d_cnt[dst[e]], 1);
}

__global__ void scan1_kernel() {
    __shared__ int sd[256];
    int t = threadIdx.x;
    int i = blockIdx.x * 256 + t;
    int v = (i < N_NODES) ? d_cnt[i] : 0;
    sd[t] = v;
    __syncthreads();
#pragma unroll
    for (int off = 1; off < 256; off <<= 1) {
        int a = (t >= off) ? sd[t - off] : 0;
        __syncthreads();
        sd[t] += a;
        __syncthreads();
    }
    if (i < N_NODES) d_row[i] = sd[t] - v;   // exclusive
    if (t == 255) d_bsum[blockIdx.x] = sd[t];
}

__global__ void scan2_kernel() {
    __shared__ int sd[256];
    int t = threadIdx.x;
    int v = (t < SCAN_BLOCKS) ? d_bsum[t] : 0;
    sd[t] = v;
    __syncthreads();
#pragma unroll
    for (int off = 1; off < 256; off <<= 1) {
        int a = (t >= off) ? sd[t - off] : 0;
        __syncthreads();
        sd[t] += a;
        __syncthreads();
    }
    if (t < SCAN_BLOCKS) d_bsum[t] = sd[t] - v;  // exclusive
}

// scan3 also self-resets d_cnt and d_gsum (replaces init_kernel; ncu-verified
// to cost ~0: 5.34us in R16 vs ~5us without the resets).
__global__ void scan3_kernel() {
    int i = blockIdx.x * blockDim.x + threadIdx.x;
    if (i < N_NODES) {
        int r = d_row[i] + d_bsum[blockIdx.x];
        d_row[i] = r;
        d_cur[i] = r;
        int c = d_cnt[i];
        d_deg[i] = (c > 0) ? (1.0f / (float)c) : 0.0f;
        d_cnt[i] = 0;                  // self-reset for next replay
    }
    if (i == 0) d_row[N_NODES] = N_EDGES;
    if (i < HIDDEN) d_gsum[i] = 0.0f;  // reset before reduce accumulates
}

__global__ void fill_kernel(const int* __restrict__ src, const int* __restrict__ dst) {
    int e = blockIdx.x * blockDim.x + threadIdx.x;
    if (e < N_EDGES) {
        int d = dst[e];
        int pos = atomicAdd(&d_cur[d], 1);
        d_colA[pos] = src[e];
    }
}

// ---------------------------------------------------------------------------
// h0 = x @ Wp + bp   (x: [N,64], Wp: [64,128]) -> d_hbuf0
// 128 threads, 32 nodes; thread (nt,ct) owns 8 nodes x 4 cols.
__global__ void __launch_bounds__(128) proj_kernel(const float* __restrict__ x,
                            const float* __restrict__ Wp,
                            const float* __restrict__ bp) {
    __shared__ float xs[32][NODE_DIM];
    int t = threadIdx.x;
    int node0 = blockIdx.x * 32;

    for (int i = t; i < 32 * (NODE_DIM / 4); i += 128) {
        int r = i >> 4;
        int c4 = i & 15;
        int node = node0 + r;
        float4 v = make_float4(0.f, 0.f, 0.f, 0.f);
        if (node < N_NODES)
            v = ((const float4*)(x + (size_t)node * NODE_DIM))[c4];
        *(float4*)&xs[r][c4 * 4] = v;
    }
    __syncthreads();

    int ct = t & 31;
    int nt = t >> 5;
    int colb = ct * 4;

    u64 acc2[8][2];
#pragma unroll
    for (int i = 0; i < 8; i++) { acc2[i][0] = 0ull; acc2[i][1] = 0ull; }

    const float4* W4 = (const float4*)Wp;
#pragma unroll 4
    for (int k = 0; k < NODE_DIM; k++) {
        float4 w = W4[k * 32 + ct];
        u64 wp0 = pack2(w.x, w.y);
        u64 wp1 = pack2(w.z, w.w);
#pragma unroll
        for (int i = 0; i < 8; i++) {
            float m = xs[nt * 8 + i][k];
            u64 mp = pack2(m, m);
            fma2(acc2[i][0], mp, wp0);
            fma2(acc2[i][1], mp, wp1);
        }
    }

    float4 bv = ((const float4*)bp)[ct];
#pragma unroll
    for (int i = 0; i < 8; i++) {
        int node = node0 + nt * 8 + i;
        if (node < N_NODES) {
            float4 r;
            unpack2(acc2[i][0], r.x, r.y);
            unpack2(acc2[i][1], r.z, r.w);
            r.x += bv.x; r.y += bv.y; r.z += bv.z; r.w += bv.w;
            *(float4*)(d_hbuf0 + (size_t)node * HIDDEN + colb) = r;
        }
    }
}

// ---------------------------------------------------------------------------
// Fused GNN layer: hout = relu(hin + (gather_mean(hin) @ Wg) + bg)
// R15-champion: two-node interleaved gather (8 LDG.128 in flight) + warp-local
// barrier (GEMM reads only own-warp ms rows) + packed-fma2 GEMM.
__global__ void __launch_bounds__(128) layer_kernel(const float* __restrict__ hin,
                             float* __restrict__ hout,
                             const float* __restrict__ Wg,
                             const float* __restrict__ bg) {
    __shared__ float ms[32][HIDDEN];
    int t = threadIdx.x;
    int node0 = blockIdx.x * 32;
    int lane = t & 31;
    int w = t >> 5;   // warp 0..3

#pragma unroll 1
    for (int ii = 0; ii < 8; ii += 2) {
        int nlA = w * 8 + ii;
        int nlB = nlA + 1;
        int nA = node0 + nlA;
        int nB = node0 + nlB;

        float4 aA0 = make_float4(0.f, 0.f, 0.f, 0.f), aA1 = aA0;
        float4 aB0 = aA0, aB1 = aA0;

        int jA = 0, eA = 0, jB = 0, eB = 0;
        float invA = 0.0f, invB = 0.0f;
        if (nA < N_NODES) { jA = d_row[nA]; eA = d_row[nA + 1]; invA = d_deg[nA]; }
        if (nB < N_NODES) { jB = d_row[nB]; eB = d_row[nB + 1]; invB = d_deg[nB]; }

        // Joint loop: 4 edges from A + 4 edges from B per iteration.
#pragma unroll 1
        while (jA + 4 <= eA && jB + 4 <= eB) {
            int sA0 = d_colA[jA],     sA1 = d_colA[jA + 1];
            int sA2 = d_colA[jA + 2], sA3 = d_colA[jA + 3];
            int sB0 = d_colA[jB],     sB1 = d_colA[jB + 1];
            int sB2 = d_colA[jB + 2], sB3 = d_colA[jB + 3];
            float4 vA0 = ((const float4*)(hin + (size_t)sA0 * HIDDEN))[lane];
            float4 vA1 = ((const float4*)(hin + (size_t)sA1 * HIDDEN))[lane];
            float4 vA2 = ((const float4*)(hin + (size_t)sA2 * HIDDEN))[lane];
            float4 vA3 = ((const float4*)(hin + (size_t)sA3 * HIDDEN))[lane];
            float4 vB0 = ((const float4*)(hin + (size_t)sB0 * HIDDEN))[lane];
            float4 vB1 = ((const float4*)(hin + (size_t)sB1 * HIDDEN))[lane];
            float4 vB2 = ((const float4*)(hin + (size_t)sB2 * HIDDEN))[lane];
            float4 vB3 = ((const float4*)(hin + (size_t)sB3 * HIDDEN))[lane];
            aA0.x += vA0.x; aA0.y += vA0.y; aA0.z += vA0.z; aA0.w += vA0.w;
            aA1.x += vA1.x; aA1.y += vA1.y; aA1.z += vA1.z; aA1.w += vA1.w;
            aA0.x += vA2.x; aA0.y += vA2.y; aA0.z += vA2.z; aA0.w += vA2.w;
            aA1.x += vA3.x; aA1.y += vA3.y; aA1.z += vA3.z; aA1.w += vA3.w;
            aB0.x += vB0.x; aB0.y += vB0.y; aB0.z += vB0.z; aB0.w += vB0.w;
            aB1.x += vB1.x; aB1.y += vB1.y; aB1.z += vB1.z; aB1.w += vB1.w;
            aB0.x += vB2.x; aB0.y += vB2.y; aB0.z += vB2.z; aB0.w += vB2.w;
            aB1.x += vB3.x; aB1.y += vB3.y; aB1.z += vB3.z; aB1.w += vB3.w;
            jA += 4; jB += 4;
        }
        // Drain A (unroll-4 then singles)
#pragma unroll 1
        while (jA + 4 <= eA) {
            int s0 = d_colA[jA],     s1 = d_colA[jA + 1];
            int s2 = d_colA[jA + 2], s3 = d_colA[jA + 3];
            float4 v0 = ((const float4*)(hin + (size_t)s0 * HIDDEN))[lane];
            float4 v1 = ((const float4*)(hin + (size_t)s1 * HIDDEN))[lane];
            float4 v2 = ((const float4*)(hin + (size_t)s2 * HIDDEN))[lane];
            float4 v3 = ((const float4*)(hin + (size_t)s3 * HIDDEN))[lane];
            aA0.x += v0.x; aA0.y += v0.y; aA0.z += v0.z; aA0.w += v0.w;
            aA1.x += v1.x; aA1.y += v1.y; aA1.z += v1.z; aA1.w += v1.w;
            aA0.x += v2.x; aA0.y += v2.y; aA0.z += v2.z; aA0.w += v2.w;
            aA1.x += v3.x; aA1.y += v3.y; aA1.z += v3.z; aA1.w += v3.w;
            jA += 4;
        }
#pragma unroll 1
        while (jA < eA) {
            int s = d_colA[jA++];
            float4 v = ((const float4*)(hin + (size_t)s * HIDDEN))[lane];
            aA0.x += v.x; aA0.y += v.y; aA0.z += v.z; aA0.w += v.w;
        }
        // Drain B
#pragma unroll 1
        while (jB + 4 <= eB) {
            int s0 = d_colA[jB],     s1 = d_colA[jB + 1];
            int s2 = d_colA[jB + 2], s3 = d_colA[jB + 3];
            float4 v0 = ((const float4*)(hin + (size_t)s0 * HIDDEN))[lane];
            float4 v1 = ((const float4*)(hin + (size_t)s1 * HIDDEN))[lane];
            float4 v2 = ((const float4*)(hin + (size_t)s2 * HIDDEN))[lane];
            float4 v3 = ((const float4*)(hin + (size_t)s3 * HIDDEN))[lane];
            aB0.x += v0.x; aB0.y += v0.y; aB0.z += v0.z; aB0.w += v0.w;
            aB1.x += v1.x; aB1.y += v1.y; aB1.z += v1.z; aB1.w += v1.w;
            aB0.x += v2.x; aB0.y += v2.y; aB0.z += v2.z; aB0.w += v2.w;
            aB1.x += v3.x; aB1.y += v3.y; aB1.z += v3.z; aB1.w += v3.w;
            jB += 4;
        }
#pragma unroll 1
        while (jB < eB) {
            int s = d_colA[jB++];
            float4 v = ((const float4*)(hin + (size_t)s * HIDDEN))[lane];
            aB0.x += v.x; aB0.y += v.y; aB0.z += v.z; aB0.w += v.w;
        }

        float4 rA, rB;
        rA.x = (aA0.x + aA1.x) * invA; rA.y = (aA0.y + aA1.y) * invA;
        rA.z = (aA0.z + aA1.z) * invA; rA.w = (aA0.w + aA1.w) * invA;
        rB.x = (aB0.x + aB1.x) * invB; rB.y = (aB0.y + aB1.y) * invB;
        rB.z = (aB0.z + aB1.z) * invB; rB.w = (aB0.w + aB1.w) * invB;
        *(float4*)&ms[nlA][lane * 4] = rA;
        *(float4*)&ms[nlB][lane * 4] = rB;
    }
    __syncwarp();   // warp-local: GEMM below reads only this warp's ms rows

    // Phase 2: (ms @ Wg) — thread (nt=w, ct=lane) owns 8 nodes x 4 cols
    int ct = lane;
    int nt = w;
    int colb = ct * 4;

    u64 acc2[8][2];
#pragma unroll
    for (int i = 0; i < 8; i++) { acc2[i][0] = 0ull; acc2[i][1] = 0ull; }

    const float4* W4 = (const float4*)Wg;
#pragma unroll 4
    for (int k = 0; k < HIDDEN; k++) {
        float4 wv = W4[k * 32 + ct];
        u64 wp0 = pack2(wv.x, wv.y);
        u64 wp1 = pack2(wv.z, wv.w);
#pragma unroll
        for (int i = 0; i < 8; i++) {
            float m = ms[nt * 8 + i][k];
            u64 mp = pack2(m, m);
            fma2(acc2[i][0], mp, wp0);
            fma2(acc2[i][1], mp, wp1);
        }
    }

    float4 bv = ((const float4*)bg)[ct];
#pragma unroll
    for (int i = 0; i < 8; i++) {
        int node = node0 + nt * 8 + i;
        if (node < N_NODES) {
            float4 hv = *(const float4*)(hin + (size_t)node * HIDDEN + colb);
            float lo, hi;
            float4 r;
            unpack2(acc2[i][0], lo, hi);
            r.x = fmaxf(hv.x + lo + bv.x, 0.0f);
            r.y = fmaxf(hv.y + hi + bv.y, 0.0f);
            unpack2(acc2[i][1], lo, hi);
            r.z = fmaxf(hv.z + lo + bv.z, 0.0f);
            r.w = fmaxf(hv.w + hi + bv.w, 0.0f);
            *(float4*)(hout + (size_t)node * HIDDEN + colb) = r;
        }
    }
}

// ---------------------------------------------------------------------------
// R15-exact reduce (65k atomics; measured ~12us).
__global__ void reduce_kernel(const float* __restrict__ h) {
    int t = threadIdx.x;   // 256
    int col = t & 127;
    int rh = t >> 7;
    float acc = 0.0f;
    for (int node = blockIdx.x * 2 + rh; node < N_NODES; node += gridDim.x * 2)
        acc += h[(size_t)node * HIDDEN + col];
    atomicAdd(&d_gsum[col], acc);
}

__global__ void mlp_kernel(const float* __restrict__ W1,
                           const float* __restrict__ b1,
                           const float* __restrict__ W2,
                           const float* __restrict__ b2,
                           float* __restrict__ out) {
    __shared__ float gs[HIDDEN];
    __shared__ float ts[HIDDEN];
    int t = threadIdx.x;  // 256
    if (t < HIDDEN) gs[t] = d_gsum[t] * (1.0f / (float)N_NODES);
    __syncthreads();
    if (t < HIDDEN) {
        float a = b1[t];
#pragma unroll 8
        for (int k = 0; k < HIDDEN; k++) a += gs[k] * W1[k * HIDDEN + t];
        ts[t] = fmaxf(a, 0.0f);
    }
    __syncthreads();
    {
        float a = b2[t];
#pragma unroll 8
        for (int k = 0; k < HIDDEN; k++) a += ts[k] * W2[k * OUT_DIM + t];
        out[t] = a;
    }
}

// ---------------------------------------------------------------------------
extern "C" void kernel_launch(void* const* d_in, const int* in_sizes, int n_in,
                              void* d_out, int out_size) {
    const float* x   = (const float*)d_in[0];
    const int*   src = (const int*)d_in[1];
    const int*   dst = (const int*)d_in[2];
    const float* Wp  = (const float*)d_in[3];
    const float* bp  = (const float*)d_in[4];
    const float* Wg  = (const float*)d_in[5];
    const float* bg  = (const float*)d_in[6];
    const float* W1  = (const float*)d_in[7];
    const float* b1  = (const float*)d_in[8];
    const float* W2  = (const float*)d_in[9];
    const float* b2  = (const float*)d_in[10];
    float* out = (float*)d_out;

    float *h0, *h1;
    cudaGetSymbolAddress((void**)&h0, d_hbuf0);
    cudaGetSymbolAddress((void**)&h1, d_hbuf1);

    // CSR build (init folded into scan3)
    hist_kernel<<<(N_EDGES + 255) / 256, 256>>>(dst);
    scan1_kernel<<<SCAN_BLOCKS, 256>>>();
    scan2_kernel<<<1, 256>>>();
    scan3_kernel<<<SCAN_BLOCKS, 256>>>();
    fill_kernel<<<(N_EDGES + 255) / 256, 256>>>(src, dst);

    // node projection
    proj_kernel<<<(N_NODES + 31) / 32, 128>>>(x, Wp, bp);

    // GNN layers with ping-pong buffers
    const int nblocks = (N_NODES + 31) / 32;
    float* bufs[2] = {h0, h1};
    for (int l = 0; l < N_LAYERS; l++) {
        float* hin  = bufs[l & 1];
        float* hout = bufs[(l + 1) & 1];
        layer_kernel<<<nblocks, 128>>>(hin, hout,
                                       Wg + (size_t)l * HIDDEN * HIDDEN,
                                       bg + (size_t)l * HIDDEN);
    }

    // mean over nodes + MLP head
    reduce_kernel<<<256, 256>>>(bufs[N_LAYERS & 1]);
    mlp_kernel<<<1, 256>>>(W1, b1, W2, b2, out);
}